// round 12
// baseline (speedup 1.0000x reference)
#include <cuda_runtime.h>
#include <cuda_bf16.h>
#include <cstdint>
#include <cstddef>

// Problem constants
#define B_   32
#define T_   2048
#define D_   256
#define H_   256
#define CS_  32
#define NN_  8
#define G_   1040      // 4*H + 2*N
#define GP_  1152      // padded to 9 tiles of 128
#define KK_  512       // D + H
#define M_   4096      // 2 dirs * 2048 lanes

// ---------------- static device scratch ----------------
__device__ __nv_bfloat16 g_Whi[2][GP_][KK_];   // [dir][g][k]; dir1 input cols feature-reversed
__device__ __nv_bfloat16 g_Wlo[2][GP_][KK_];
__device__ __nv_bfloat16 g_xhi[(size_t)B_ * T_ * D_];
__device__ __nv_bfloat16 g_xlo[(size_t)B_ * T_ * D_];
__device__ __nv_bfloat16 g_hhi[2 * T_ * H_];
__device__ __nv_bfloat16 g_hlo[2 * T_ * H_];
__device__ float g_c[2 * T_ * H_];
__device__ float g_bias[GP_];
__device__ float g_tin[(size_t)(2 * B_ * T_) * GP_];   // input projection (raw, bias in step epilogue)
__device__ float g_gates[(size_t)M_ * GP_];
__device__ int   g_off[B_];
__device__ int   g_sl[B_];

// ---------------- helpers ----------------
__device__ __forceinline__ uint32_t smem_u32(const void* p) {
    uint32_t a;
    asm("{ .reg .u64 t; cvta.to.shared.u64 t, %1; cvt.u32.u64 %0, t; }" : "=r"(a) : "l"(p));
    return a;
}
__device__ __forceinline__ void ldsm_x4(uint32_t* r, uint32_t addr) {
    asm volatile("ldmatrix.sync.aligned.m8n8.x4.shared.b16 {%0,%1,%2,%3}, [%4];"
        : "=r"(r[0]), "=r"(r[1]), "=r"(r[2]), "=r"(r[3]) : "r"(addr));
}
__device__ __forceinline__ void mma16816(float* c, const uint32_t* a, const uint32_t* b) {
    asm volatile("mma.sync.aligned.m16n8k16.row.col.f32.bf16.bf16.f32 "
        "{%0,%1,%2,%3}, {%4,%5,%6,%7}, {%8,%9}, {%0,%1,%2,%3};"
        : "+f"(c[0]), "+f"(c[1]), "+f"(c[2]), "+f"(c[3])
        : "r"(a[0]), "r"(a[1]), "r"(a[2]), "r"(a[3]), "r"(b[0]), "r"(b[1]));
}
__device__ __forceinline__ float sigmoidf_(float xx) { return 1.f / (1.f + __expf(-xx)); }
__device__ __forceinline__ float tanhf_(float xx)    { return 1.f - 2.f / (1.f + __expf(2.f * xx)); }

// ---------------- prep ----------------
__global__ void prep_kernel(const float* __restrict__ x,
                            const float* __restrict__ W_ih, const float* __restrict__ b_ih,
                            const float* __restrict__ W_hh, const float* __restrict__ b_hh,
                            const void* __restrict__ sl_raw) {
    int tid = blockIdx.x * blockDim.x + threadIdx.x;
    int stride = gridDim.x * blockDim.x;
    for (int i = tid; i < 2 * GP_ * KK_; i += stride) {
        int dir = i / (GP_ * KK_);
        int r   = i % (GP_ * KK_);
        int g = r / KK_, k = r % KK_;
        float v = 0.f;
        if (g < G_) {
            if (k < D_) v = W_ih[g * D_ + (dir ? (D_ - 1 - k) : k)];
            else        v = W_hh[g * H_ + (k - D_)];
        }
        __nv_bfloat16 hi = __float2bfloat16(v);
        g_Whi[dir][g][k] = hi;
        g_Wlo[dir][g][k] = __float2bfloat16(v - __bfloat162float(hi));
    }
    for (size_t i = tid; i < (size_t)B_ * T_ * D_; i += stride) {
        float v = x[i];
        __nv_bfloat16 hi = __float2bfloat16(v);
        g_xhi[i] = hi;
        g_xlo[i] = __float2bfloat16(v - __bfloat162float(hi));
    }
    for (int i = tid; i < 2 * T_ * H_; i += stride) {
        g_hhi[i] = __float2bfloat16(0.f);
        g_hlo[i] = __float2bfloat16(0.f);
        g_c[i] = 0.f;
    }
    if (tid < GP_) g_bias[tid] = (tid < G_) ? (b_ih[tid] + b_hh[tid]) : 0.f;
    if (tid == 0) {
        const int* s32 = (const int*)sl_raw;
        const long long* s64 = (const long long*)sl_raw;
        bool is64 = (s32[1] == 0);
        int acc = 0;
        for (int b = 0; b < B_; b++) {
            int v = is64 ? (int)s64[b] : s32[b];
            g_sl[b] = v; g_off[b] = acc; acc += v;
        }
    }
}

// ---------------- FROZEN step GEMM (bf16 3-term split, R4 structure) ----------------
// gates[m][g] = sum_k h[m][k] * W_hh'[g][k] + t_in + bias, K=256.
__global__ __launch_bounds__(256) void step_gemm(int bidx) {
    __shared__ __align__(16) __nv_bfloat16 As[2][128][40];   // hi, lo
    __shared__ __align__(16) __nv_bfloat16 Bs[2][128][40];

    int tid = threadIdx.x, lane = tid & 31, wid = tid >> 5;
    int wm = wid & 3, wn = wid >> 2;
    int n0 = blockIdx.x * 128;
    int m0 = blockIdx.y * 128;

    int dir = m0 >> 11;
    int t0  = m0 & (T_ - 1);
    const __nv_bfloat16* Ahi_g = g_hhi + ((size_t)dir * T_ + t0) * H_;
    const __nv_bfloat16* Alo_g = g_hlo + ((size_t)dir * T_ + t0) * H_;
    const int kofsW = D_;

    float acc[2][8][4];
#pragma unroll
    for (int im = 0; im < 2; im++)
#pragma unroll
        for (int in_ = 0; in_ < 8; in_++)
#pragma unroll
            for (int j = 0; j < 4; j++) acc[im][in_][j] = 0.f;

    for (int k0 = 0; k0 < 256; k0 += 32) {
#pragma unroll
        for (int i = 0; i < 8; i++) {
            int s = tid + i * 256;
            int tile = s >> 9;
            int idx  = s & 511;
            int r  = idx >> 2;
            int ks = (idx & 3) * 8;
            const __nv_bfloat16* src;
            if      (tile == 0) src = Ahi_g + (size_t)r * 256 + k0 + ks;
            else if (tile == 1) src = Alo_g + (size_t)r * 256 + k0 + ks;
            else if (tile == 2) src = &g_Whi[dir][n0 + r][kofsW + k0 + ks];
            else                src = &g_Wlo[dir][n0 + r][kofsW + k0 + ks];
            uint4 v = *(const uint4*)src;
            __nv_bfloat16* dst = (tile == 0) ? &As[0][r][ks] :
                                 (tile == 1) ? &As[1][r][ks] :
                                 (tile == 2) ? &Bs[0][r][ks] : &Bs[1][r][ks];
            *(uint4*)dst = v;
        }
        __syncthreads();

#pragma unroll
        for (int kk = 0; kk < 32; kk += 16) {
            uint32_t ah[2][4], al[2][4], bh[4][4], bl[4][4];
#pragma unroll
            for (int im = 0; im < 2; im++) {
                int arow = wm * 32 + im * 16 + (lane & 15);
                int acol = kk + ((lane >> 4) << 3);
                ldsm_x4(ah[im], smem_u32(&As[0][arow][acol]));
                ldsm_x4(al[im], smem_u32(&As[1][arow][acol]));
            }
#pragma unroll
            for (int p = 0; p < 4; p++) {
                int brow = wn * 64 + p * 16 + (lane & 7) + ((lane >> 4) & 1) * 8;
                int bcol = kk + (((lane >> 3) & 1) << 3);
                ldsm_x4(bh[p], smem_u32(&Bs[0][brow][bcol]));
                ldsm_x4(bl[p], smem_u32(&Bs[1][brow][bcol]));
            }
#pragma unroll
            for (int im = 0; im < 2; im++)
#pragma unroll
                for (int in_ = 0; in_ < 8; in_++) {
                    const uint32_t* B0 = &bh[in_ >> 1][(in_ & 1) * 2];
                    const uint32_t* B1 = &bl[in_ >> 1][(in_ & 1) * 2];
                    mma16816(acc[im][in_], ah[im], B0);   // hi*hi
                    mma16816(acc[im][in_], ah[im], B1);   // hi*lo
                    mma16816(acc[im][in_], al[im], B0);   // lo*hi
                }
        }
        __syncthreads();
    }

#pragma unroll
    for (int im = 0; im < 2; im++)
#pragma unroll
        for (int in_ = 0; in_ < 8; in_++) {
            int row = m0 + wm * 32 + im * 16 + (lane >> 2);
            int col = n0 + wn * 64 + in_ * 8 + ((lane & 3) << 1);
            if (col >= G_) continue;
            float* c = acc[im][in_];
            int t = row & (T_ - 1);
            int d = row >> 11;
            size_t trow = (size_t)(d * 65536 + bidx * 2048 + t);
            float2 t0v = *(const float2*)&g_tin[trow * GP_ + col];
            float2 t1v = *(const float2*)&g_tin[(trow + 8) * GP_ + col];
            float2 bb = *(const float2*)&g_bias[col];
            *(float2*)&g_gates[(size_t)row * GP_ + col] =
                make_float2(c[0] + t0v.x + bb.x, c[1] + t0v.y + bb.y);
            *(float2*)&g_gates[(size_t)(row + 8) * GP_ + col] =
                make_float2(c[2] + t1v.x + bb.x, c[3] + t1v.y + bb.y);
        }
}

// ---------------- proj GEMM body (per-batch chunk) as device function ----------------
// Computes t_in rows for batch bn: local row space 0..4095 (dir*2048 + t).
__device__ void proj_tile(int bn, int n0, int m0l) {
    __shared__ __align__(16) __nv_bfloat16 As[2][128][40];
    __shared__ __align__(16) __nv_bfloat16 Bs[2][128][40];

    int tid = threadIdx.x, lane = tid & 31, wid = tid >> 5;
    int wm = wid & 3, wn = wid >> 2;

    int dir = m0l >> 11;
    int t0  = m0l & (T_ - 1);
    const __nv_bfloat16* Ahi_g = g_xhi + ((size_t)bn * T_ + t0) * D_;
    const __nv_bfloat16* Alo_g = g_xlo + ((size_t)bn * T_ + t0) * D_;

    float acc[2][8][4];
#pragma unroll
    for (int im = 0; im < 2; im++)
#pragma unroll
        for (int in_ = 0; in_ < 8; in_++)
#pragma unroll
            for (int j = 0; j < 4; j++) acc[im][in_][j] = 0.f;

    for (int k0 = 0; k0 < 256; k0 += 32) {
#pragma unroll
        for (int i = 0; i < 8; i++) {
            int s = tid + i * 256;
            int tile = s >> 9;
            int idx  = s & 511;
            int r  = idx >> 2;
            int ks = (idx & 3) * 8;
            const __nv_bfloat16* src;
            if      (tile == 0) src = Ahi_g + (size_t)r * 256 + k0 + ks;
            else if (tile == 1) src = Alo_g + (size_t)r * 256 + k0 + ks;
            else if (tile == 2) src = &g_Whi[dir][n0 + r][k0 + ks];
            else                src = &g_Wlo[dir][n0 + r][k0 + ks];
            uint4 v = *(const uint4*)src;
            __nv_bfloat16* dst = (tile == 0) ? &As[0][r][ks] :
                                 (tile == 1) ? &As[1][r][ks] :
                                 (tile == 2) ? &Bs[0][r][ks] : &Bs[1][r][ks];
            *(uint4*)dst = v;
        }
        __syncthreads();

#pragma unroll
        for (int kk = 0; kk < 32; kk += 16) {
            uint32_t ah[2][4], al[2][4], bh[4][4], bl[4][4];
#pragma unroll
            for (int im = 0; im < 2; im++) {
                int arow = wm * 32 + im * 16 + (lane & 15);
                int acol = kk + ((lane >> 4) << 3);
                ldsm_x4(ah[im], smem_u32(&As[0][arow][acol]));
                ldsm_x4(al[im], smem_u32(&As[1][arow][acol]));
            }
#pragma unroll
            for (int p = 0; p < 4; p++) {
                int brow = wn * 64 + p * 16 + (lane & 7) + ((lane >> 4) & 1) * 8;
                int bcol = kk + (((lane >> 3) & 1) << 3);
                ldsm_x4(bh[p], smem_u32(&Bs[0][brow][bcol]));
                ldsm_x4(bl[p], smem_u32(&Bs[1][brow][bcol]));
            }
#pragma unroll
            for (int im = 0; im < 2; im++)
#pragma unroll
                for (int in_ = 0; in_ < 8; in_++) {
                    const uint32_t* B0 = &bh[in_ >> 1][(in_ & 1) * 2];
                    const uint32_t* B1 = &bl[in_ >> 1][(in_ & 1) * 2];
                    mma16816(acc[im][in_], ah[im], B0);
                    mma16816(acc[im][in_], ah[im], B1);
                    mma16816(acc[im][in_], al[im], B0);
                }
        }
        __syncthreads();
    }

#pragma unroll
    for (int im = 0; im < 2; im++)
#pragma unroll
        for (int in_ = 0; in_ < 8; in_++) {
            int rowl = m0l + wm * 32 + im * 16 + (lane >> 2);
            int col = n0 + wn * 64 + in_ * 8 + ((lane & 3) << 1);
            if (col >= G_) continue;
            float* c = acc[im][in_];
            int t = rowl & (T_ - 1);
            int d = rowl >> 11;
            size_t trow = (size_t)(d * 65536 + bn * 2048 + t);
            *(float2*)&g_tin[trow * GP_ + col] = make_float2(c[0], c[1]);
            *(float2*)&g_tin[(trow + 8) * GP_ + col] = make_float2(c[2], c[3]);
        }
}

// standalone proj chunk (used for batch 0 before the loop)
__global__ __launch_bounds__(256) void proj_chunk(int bn) {
    proj_tile(bn, blockIdx.x * 128, blockIdx.y * 128);
}

// ---------------- step 0 shortcut: gates = t_in + bias (h == 0) ----------------
__global__ __launch_bounds__(256) void gates_from_tin(int bidx) {
    int row = blockIdx.x;                  // 0..4095
    int t = row & (T_ - 1);
    int d = row >> 11;
    size_t trow = (size_t)(d * 65536 + bidx * 2048 + t);
    const float* src = &g_tin[trow * GP_];
    float* dst = &g_gates[(size_t)row * GP_];
    for (int c = threadIdx.x * 4; c < G_; c += 1024) {
        float4 v = *(const float4*)&src[c];
        float4 bb = *(const float4*)&g_bias[c];
        *(float4*)&dst[c] = make_float4(v.x + bb.x, v.y + bb.y, v.z + bb.z, v.w + bb.w);
    }
}

// ---------------- fused: gate update for step b (blocks 0..511) + proj chunk for bnext ----
__global__ __launch_bounds__(256) void fused_gate_proj(float* __restrict__ out, int b, int bnext) {
    if (blockIdx.x >= 512) {
        if (bnext < B_) {
            int vb = blockIdx.x - 512;     // 0..287
            proj_tile(bnext, (vb % 9) * 128, (vb / 9) * 128);
        }
        return;
    }

    // ---- gate path: 1 warp per row ----
    int lane = threadIdx.x & 31;
    int wid  = threadIdx.x >> 5;
    int row  = blockIdx.x * 8 + wid;       // 0..4095
    int dir  = row >> 11;
    int t    = row & (T_ - 1);
    const float* grow = &g_gates[(size_t)row * GP_];

    int sl_b = g_sl[b];
    int off_b = g_off[b];

    float v = (lane < 16) ? grow[lane] : 0.f;
    float mx = v;
#pragma unroll
    for (int o = 4; o; o >>= 1) mx = fmaxf(mx, __shfl_xor_sync(0xffffffff, mx, o, 8));
    float e = __expf(v - mx);
    float sum = e;
#pragma unroll
    for (int o = 4; o; o >>= 1) sum += __shfl_xor_sync(0xffffffff, sum, o, 8);
    float cs = e;
#pragma unroll
    for (int o = 1; o < 8; o <<= 1) {
        float u = __shfl_up_sync(0xffffffff, cs, o, 8);
        if ((lane & 7) >= o) cs += u;
    }
    float cum = cs / sum;
    float mval = (lane < 8) ? (1.f - cum) : cum;   // cin | cfg

#pragma unroll
    for (int j = 0; j < 8; j++) {
        float ci = __shfl_sync(0xffffffff, mval, j);
        float cf = __shfl_sync(0xffffffff, mval, 8 + j);
        int colr = j * 32 + lane;
        float og = grow[16 + colr];
        float cg = grow[16 + 256 + colr];
        float ig = grow[16 + 512 + colr];
        float fg = grow[16 + 768 + colr];
        float ov = cf * ci;
        float fv = sigmoidf_(fg) * ov + (cf - ov);
        float iv = sigmoidf_(ig) * ov + (ci - ov);
        size_t hidx = ((size_t)dir * T_ + t) * H_ + colr;
        float cy = fv * g_c[hidx] + iv * tanhf_(cg);
        g_c[hidx] = cy;
        float hy = sigmoidf_(og) * tanhf_(cy);
        __nv_bfloat16 hi = __float2bfloat16(hy);
        g_hhi[hidx] = hi;
        g_hlo[hidx] = __float2bfloat16(hy - __bfloat162float(hi));
        if (t < sl_b) {
            out[((size_t)(off_b + t)) * (2 * H_) + dir * H_ + colr] = hy;
        }
    }
}

// ---------------- launch ----------------
extern "C" void kernel_launch(void* const* d_in, const int* in_sizes, int n_in,
                              void* d_out, int out_size) {
    const float* x    = (const float*)d_in[0];
    const void*  sl   = d_in[1];
    const float* W_ih = (const float*)d_in[2];
    const float* b_ih = (const float*)d_in[3];
    const float* W_hh = (const float*)d_in[4];
    const float* b_hh = (const float*)d_in[5];
    float*       out  = (float*)d_out;

    prep_kernel<<<4096, 256>>>(x, W_ih, b_ih, W_hh, b_hh, sl);

    proj_chunk<<<dim3(GP_ / 128, M_ / 128), 256>>>(0);    // t_in for batch 0

    for (int b = 0; b < B_; b++) {
        if (b == 0) gates_from_tin<<<M_, 256>>>(0);       // h == 0: no recurrent GEMM
        else        step_gemm<<<dim3(GP_ / 128, M_ / 128), 256>>>(b);
        fused_gate_proj<<<800, 256>>>(out, b, b + 1);     // gate(b) + proj(b+1)
    }
}

// round 13
// speedup vs baseline: 1.1540x; 1.1540x over previous
#include <cuda_runtime.h>
#include <cuda_bf16.h>
#include <cstdint>
#include <cstddef>

// Problem constants
#define B_   32
#define T_   2048
#define D_   256
#define H_   256
#define CS_  32
#define NN_  8
#define G_   1040      // 4*H + 2*N
#define GP_  1152      // padded to 9 tiles of 128
#define KK_  512       // D + H
#define M_   4096      // 2 dirs * 2048 lanes

// ---------------- static device scratch ----------------
__device__ __nv_bfloat16 g_Whi[2][GP_][KK_];   // [dir][g][k]; dir1 input cols feature-reversed
__device__ __nv_bfloat16 g_Wlo[2][GP_][KK_];
__device__ __nv_bfloat16 g_xhi[(size_t)B_ * T_ * D_];
__device__ __nv_bfloat16 g_xlo[(size_t)B_ * T_ * D_];
__device__ __nv_bfloat16 g_hhi[2 * T_ * H_];
__device__ __nv_bfloat16 g_hlo[2 * T_ * H_];
__device__ float g_c[2 * T_ * H_];
__device__ float g_bias[GP_];
__device__ float g_tin[(size_t)(2 * B_ * T_) * GP_];   // input projection (raw)
__device__ float g_gates[(size_t)M_ * GP_];
__device__ int   g_off[B_];
__device__ int   g_sl[B_];

// ---------------- helpers ----------------
__device__ __forceinline__ uint32_t smem_u32(const void* p) {
    uint32_t a;
    asm("{ .reg .u64 t; cvta.to.shared.u64 t, %1; cvt.u32.u64 %0, t; }" : "=r"(a) : "l"(p));
    return a;
}
__device__ __forceinline__ void ldsm_x4(uint32_t* r, uint32_t addr) {
    asm volatile("ldmatrix.sync.aligned.m8n8.x4.shared.b16 {%0,%1,%2,%3}, [%4];"
        : "=r"(r[0]), "=r"(r[1]), "=r"(r[2]), "=r"(r[3]) : "r"(addr));
}
__device__ __forceinline__ void mma16816(float* c, const uint32_t* a, const uint32_t* b) {
    asm volatile("mma.sync.aligned.m16n8k16.row.col.f32.bf16.bf16.f32 "
        "{%0,%1,%2,%3}, {%4,%5,%6,%7}, {%8,%9}, {%0,%1,%2,%3};"
        : "+f"(c[0]), "+f"(c[1]), "+f"(c[2]), "+f"(c[3])
        : "r"(a[0]), "r"(a[1]), "r"(a[2]), "r"(a[3]), "r"(b[0]), "r"(b[1]));
}
__device__ __forceinline__ float sigmoidf_(float xx) { return 1.f / (1.f + __expf(-xx)); }
__device__ __forceinline__ float tanhf_(float xx)    { return 1.f - 2.f / (1.f + __expf(2.f * xx)); }

// ---------------- prep ----------------
__global__ void prep_kernel(const float* __restrict__ x,
                            const float* __restrict__ W_ih, const float* __restrict__ b_ih,
                            const float* __restrict__ W_hh, const float* __restrict__ b_hh,
                            const void* __restrict__ sl_raw) {
    int tid = blockIdx.x * blockDim.x + threadIdx.x;
    int stride = gridDim.x * blockDim.x;
    for (int i = tid; i < 2 * GP_ * KK_; i += stride) {
        int dir = i / (GP_ * KK_);
        int r   = i % (GP_ * KK_);
        int g = r / KK_, k = r % KK_;
        float v = 0.f;
        if (g < G_) {
            if (k < D_) v = W_ih[g * D_ + (dir ? (D_ - 1 - k) : k)];
            else        v = W_hh[g * H_ + (k - D_)];
        }
        __nv_bfloat16 hi = __float2bfloat16(v);
        g_Whi[dir][g][k] = hi;
        g_Wlo[dir][g][k] = __float2bfloat16(v - __bfloat162float(hi));
    }
    for (size_t i = tid; i < (size_t)B_ * T_ * D_; i += stride) {
        float v = x[i];
        __nv_bfloat16 hi = __float2bfloat16(v);
        g_xhi[i] = hi;
        g_xlo[i] = __float2bfloat16(v - __bfloat162float(hi));
    }
    for (int i = tid; i < 2 * T_ * H_; i += stride) {
        g_hhi[i] = __float2bfloat16(0.f);
        g_hlo[i] = __float2bfloat16(0.f);
        g_c[i] = 0.f;
    }
    if (tid < GP_) g_bias[tid] = (tid < G_) ? (b_ih[tid] + b_hh[tid]) : 0.f;
    if (tid == 0) {
        const int* s32 = (const int*)sl_raw;
        const long long* s64 = (const long long*)sl_raw;
        bool is64 = (s32[1] == 0);
        int acc = 0;
        for (int b = 0; b < B_; b++) {
            int v = is64 ? (int)s64[b] : s32[b];
            g_sl[b] = v; g_off[b] = acc; acc += v;
        }
    }
}

// ---------------- FROZEN step GEMM (bf16 3-term split, R4 structure) ----------------
__global__ __launch_bounds__(256) void step_gemm(int bidx) {
    __shared__ __align__(16) __nv_bfloat16 As[2][128][40];   // hi, lo
    __shared__ __align__(16) __nv_bfloat16 Bs[2][128][40];

    int tid = threadIdx.x, lane = tid & 31, wid = tid >> 5;
    int wm = wid & 3, wn = wid >> 2;
    int n0 = blockIdx.x * 128;
    int m0 = blockIdx.y * 128;

    int dir = m0 >> 11;
    int t0  = m0 & (T_ - 1);
    const __nv_bfloat16* Ahi_g = g_hhi + ((size_t)dir * T_ + t0) * H_;
    const __nv_bfloat16* Alo_g = g_hlo + ((size_t)dir * T_ + t0) * H_;
    const int kofsW = D_;

    float acc[2][8][4];
#pragma unroll
    for (int im = 0; im < 2; im++)
#pragma unroll
        for (int in_ = 0; in_ < 8; in_++)
#pragma unroll
            for (int j = 0; j < 4; j++) acc[im][in_][j] = 0.f;

    for (int k0 = 0; k0 < 256; k0 += 32) {
#pragma unroll
        for (int i = 0; i < 8; i++) {
            int s = tid + i * 256;
            int tile = s >> 9;
            int idx  = s & 511;
            int r  = idx >> 2;
            int ks = (idx & 3) * 8;
            const __nv_bfloat16* src;
            if      (tile == 0) src = Ahi_g + (size_t)r * 256 + k0 + ks;
            else if (tile == 1) src = Alo_g + (size_t)r * 256 + k0 + ks;
            else if (tile == 2) src = &g_Whi[dir][n0 + r][kofsW + k0 + ks];
            else                src = &g_Wlo[dir][n0 + r][kofsW + k0 + ks];
            uint4 v = *(const uint4*)src;
            __nv_bfloat16* dst = (tile == 0) ? &As[0][r][ks] :
                                 (tile == 1) ? &As[1][r][ks] :
                                 (tile == 2) ? &Bs[0][r][ks] : &Bs[1][r][ks];
            *(uint4*)dst = v;
        }
        __syncthreads();

#pragma unroll
        for (int kk = 0; kk < 32; kk += 16) {
            uint32_t ah[2][4], al[2][4], bh[4][4], bl[4][4];
#pragma unroll
            for (int im = 0; im < 2; im++) {
                int arow = wm * 32 + im * 16 + (lane & 15);
                int acol = kk + ((lane >> 4) << 3);
                ldsm_x4(ah[im], smem_u32(&As[0][arow][acol]));
                ldsm_x4(al[im], smem_u32(&As[1][arow][acol]));
            }
#pragma unroll
            for (int p = 0; p < 4; p++) {
                int brow = wn * 64 + p * 16 + (lane & 7) + ((lane >> 4) & 1) * 8;
                int bcol = kk + (((lane >> 3) & 1) << 3);
                ldsm_x4(bh[p], smem_u32(&Bs[0][brow][bcol]));
                ldsm_x4(bl[p], smem_u32(&Bs[1][brow][bcol]));
            }
#pragma unroll
            for (int im = 0; im < 2; im++)
#pragma unroll
                for (int in_ = 0; in_ < 8; in_++) {
                    const uint32_t* B0 = &bh[in_ >> 1][(in_ & 1) * 2];
                    const uint32_t* B1 = &bl[in_ >> 1][(in_ & 1) * 2];
                    mma16816(acc[im][in_], ah[im], B0);   // hi*hi
                    mma16816(acc[im][in_], ah[im], B1);   // hi*lo
                    mma16816(acc[im][in_], al[im], B0);   // lo*hi
                }
        }
        __syncthreads();
    }

#pragma unroll
    for (int im = 0; im < 2; im++)
#pragma unroll
        for (int in_ = 0; in_ < 8; in_++) {
            int row = m0 + wm * 32 + im * 16 + (lane >> 2);
            int col = n0 + wn * 64 + in_ * 8 + ((lane & 3) << 1);
            if (col >= G_) continue;
            float* c = acc[im][in_];
            int t = row & (T_ - 1);
            int d = row >> 11;
            size_t trow = (size_t)(d * 65536 + bidx * 2048 + t);
            float2 t0v = *(const float2*)&g_tin[trow * GP_ + col];
            float2 t1v = *(const float2*)&g_tin[(trow + 8) * GP_ + col];
            float2 bb = *(const float2*)&g_bias[col];
            *(float2*)&g_gates[(size_t)row * GP_ + col] =
                make_float2(c[0] + t0v.x + bb.x, c[1] + t0v.y + bb.y);
            *(float2*)&g_gates[(size_t)(row + 8) * GP_ + col] =
                make_float2(c[2] + t1v.x + bb.x, c[3] + t1v.y + bb.y);
        }
}

// ---------------- proj GEMM (per-batch chunk) ----------------
__device__ void proj_tile(int bn, int n0, int m0l) {
    __shared__ __align__(16) __nv_bfloat16 As[2][128][40];
    __shared__ __align__(16) __nv_bfloat16 Bs[2][128][40];

    int tid = threadIdx.x, lane = tid & 31, wid = tid >> 5;
    int wm = wid & 3, wn = wid >> 2;

    int dir = m0l >> 11;
    int t0  = m0l & (T_ - 1);
    const __nv_bfloat16* Ahi_g = g_xhi + ((size_t)bn * T_ + t0) * D_;
    const __nv_bfloat16* Alo_g = g_xlo + ((size_t)bn * T_ + t0) * D_;

    float acc[2][8][4];
#pragma unroll
    for (int im = 0; im < 2; im++)
#pragma unroll
        for (int in_ = 0; in_ < 8; in_++)
#pragma unroll
            for (int j = 0; j < 4; j++) acc[im][in_][j] = 0.f;

    for (int k0 = 0; k0 < 256; k0 += 32) {
#pragma unroll
        for (int i = 0; i < 8; i++) {
            int s = tid + i * 256;
            int tile = s >> 9;
            int idx  = s & 511;
            int r  = idx >> 2;
            int ks = (idx & 3) * 8;
            const __nv_bfloat16* src;
            if      (tile == 0) src = Ahi_g + (size_t)r * 256 + k0 + ks;
            else if (tile == 1) src = Alo_g + (size_t)r * 256 + k0 + ks;
            else if (tile == 2) src = &g_Whi[dir][n0 + r][k0 + ks];
            else                src = &g_Wlo[dir][n0 + r][k0 + ks];
            uint4 v = *(const uint4*)src;
            __nv_bfloat16* dst = (tile == 0) ? &As[0][r][ks] :
                                 (tile == 1) ? &As[1][r][ks] :
                                 (tile == 2) ? &Bs[0][r][ks] : &Bs[1][r][ks];
            *(uint4*)dst = v;
        }
        __syncthreads();

#pragma unroll
        for (int kk = 0; kk < 32; kk += 16) {
            uint32_t ah[2][4], al[2][4], bh[4][4], bl[4][4];
#pragma unroll
            for (int im = 0; im < 2; im++) {
                int arow = wm * 32 + im * 16 + (lane & 15);
                int acol = kk + ((lane >> 4) << 3);
                ldsm_x4(ah[im], smem_u32(&As[0][arow][acol]));
                ldsm_x4(al[im], smem_u32(&As[1][arow][acol]));
            }
#pragma unroll
            for (int p = 0; p < 4; p++) {
                int brow = wn * 64 + p * 16 + (lane & 7) + ((lane >> 4) & 1) * 8;
                int bcol = kk + (((lane >> 3) & 1) << 3);
                ldsm_x4(bh[p], smem_u32(&Bs[0][brow][bcol]));
                ldsm_x4(bl[p], smem_u32(&Bs[1][brow][bcol]));
            }
#pragma unroll
            for (int im = 0; im < 2; im++)
#pragma unroll
                for (int in_ = 0; in_ < 8; in_++) {
                    const uint32_t* B0 = &bh[in_ >> 1][(in_ & 1) * 2];
                    const uint32_t* B1 = &bl[in_ >> 1][(in_ & 1) * 2];
                    mma16816(acc[im][in_], ah[im], B0);
                    mma16816(acc[im][in_], ah[im], B1);
                    mma16816(acc[im][in_], al[im], B0);
                }
        }
        __syncthreads();
    }

#pragma unroll
    for (int im = 0; im < 2; im++)
#pragma unroll
        for (int in_ = 0; in_ < 8; in_++) {
            int rowl = m0l + wm * 32 + im * 16 + (lane >> 2);
            int col = n0 + wn * 64 + in_ * 8 + ((lane & 3) << 1);
            if (col >= G_) continue;
            float* c = acc[im][in_];
            int t = rowl & (T_ - 1);
            int d = rowl >> 11;
            size_t trow = (size_t)(d * 65536 + bn * 2048 + t);
            *(float2*)&g_tin[trow * GP_ + col] = make_float2(c[0], c[1]);
            *(float2*)&g_tin[(trow + 8) * GP_ + col] = make_float2(c[2], c[3]);
        }
}

__global__ __launch_bounds__(256) void proj_chunk(int bn) {
    proj_tile(bn, blockIdx.x * 128, blockIdx.y * 128);
}

// ---------------- step 0 shortcut: gates = t_in + bias (h == 0) ----------------
__global__ __launch_bounds__(256) void gates_from_tin(int bidx) {
    int row = blockIdx.x;
    int t = row & (T_ - 1);
    int d = row >> 11;
    size_t trow = (size_t)(d * 65536 + bidx * 2048 + t);
    const float* src = &g_tin[trow * GP_];
    float* dst = &g_gates[(size_t)row * GP_];
    for (int c = threadIdx.x * 4; c < G_; c += 1024) {
        float4 v = *(const float4*)&src[c];
        float4 bb = *(const float4*)&g_bias[c];
        *(float4*)&dst[c] = make_float4(v.x + bb.x, v.y + bb.y, v.z + bb.z, v.w + bb.w);
    }
}

// ---------------- per-step gate update: 1 warp per row ----------------
__global__ __launch_bounds__(256) void step_gate(float* __restrict__ out, int b) {
    int lane = threadIdx.x & 31;
    int wid  = threadIdx.x >> 5;
    int row  = blockIdx.x * 8 + wid;
    int dir  = row >> 11;
    int t    = row & (T_ - 1);
    const float* grow = &g_gates[(size_t)row * GP_];

    int sl_b = g_sl[b];
    int off_b = g_off[b];

    float v = (lane < 16) ? grow[lane] : 0.f;
    float mx = v;
#pragma unroll
    for (int o = 4; o; o >>= 1) mx = fmaxf(mx, __shfl_xor_sync(0xffffffff, mx, o, 8));
    float e = __expf(v - mx);
    float sum = e;
#pragma unroll
    for (int o = 4; o; o >>= 1) sum += __shfl_xor_sync(0xffffffff, sum, o, 8);
    float cs = e;
#pragma unroll
    for (int o = 1; o < 8; o <<= 1) {
        float u = __shfl_up_sync(0xffffffff, cs, o, 8);
        if ((lane & 7) >= o) cs += u;
    }
    float cum = cs / sum;
    float mval = (lane < 8) ? (1.f - cum) : cum;   // cin | cfg

#pragma unroll
    for (int j = 0; j < 8; j++) {
        float ci = __shfl_sync(0xffffffff, mval, j);
        float cf = __shfl_sync(0xffffffff, mval, 8 + j);
        int colr = j * 32 + lane;
        float og = grow[16 + colr];
        float cg = grow[16 + 256 + colr];
        float ig = grow[16 + 512 + colr];
        float fg = grow[16 + 768 + colr];
        float ov = cf * ci;
        float fv = sigmoidf_(fg) * ov + (cf - ov);
        float iv = sigmoidf_(ig) * ov + (ci - ov);
        size_t hidx = ((size_t)dir * T_ + t) * H_ + colr;
        float cy = fv * g_c[hidx] + iv * tanhf_(cg);
        g_c[hidx] = cy;
        float hy = sigmoidf_(og) * tanhf_(cy);
        __nv_bfloat16 hi = __float2bfloat16(hy);
        g_hhi[hidx] = hi;
        g_hlo[hidx] = __float2bfloat16(hy - __bfloat162float(hi));
        if (t < sl_b) {
            out[((size_t)(off_b + t)) * (2 * H_) + dir * H_ + colr] = hy;
        }
    }
}

// ---------------- launch: two-stream graph (proj branch overlaps step loop) ----------------
extern "C" void kernel_launch(void* const* d_in, const int* in_sizes, int n_in,
                              void* d_out, int out_size) {
    const float* x    = (const float*)d_in[0];
    const void*  sl   = d_in[1];
    const float* W_ih = (const float*)d_in[2];
    const float* b_ih = (const float*)d_in[3];
    const float* W_hh = (const float*)d_in[4];
    const float* b_hh = (const float*)d_in[5];
    float*       out  = (float*)d_out;

    cudaStream_t s2;
    cudaStreamCreate(&s2);
    cudaEvent_t evFork;
    cudaEvent_t evProj[B_];
    cudaEventCreateWithFlags(&evFork, cudaEventDisableTiming);
    for (int b = 1; b < B_; b++) cudaEventCreateWithFlags(&evProj[b], cudaEventDisableTiming);

    prep_kernel<<<4096, 256>>>(x, W_ih, b_ih, W_hh, b_hh, sl);
    cudaEventRecord(evFork, 0);
    cudaStreamWaitEvent(s2, evFork, 0);

    proj_chunk<<<dim3(GP_ / 128, M_ / 128), 256>>>(0);        // batch 0 on main stream

    for (int b = 1; b < B_; b++) {                            // batches 1..31 on side stream
        proj_chunk<<<dim3(GP_ / 128, M_ / 128), 256, 0, s2>>>(b);
        cudaEventRecord(evProj[b], s2);
    }

    for (int b = 0; b < B_; b++) {
        if (b == 0) {
            gates_from_tin<<<M_, 256>>>(0);
        } else {
            cudaStreamWaitEvent(0, evProj[b], 0);             // join proj(b) before its step
            step_gemm<<<dim3(GP_ / 128, M_ / 128), 256>>>(b);
        }
        step_gate<<<512, 256>>>(out, b);
    }
    // evProj[31] wait above joins s2's branch into the main stream; capture ends cleanly.
}